// round 2
// baseline (speedup 1.0000x reference)
#include <cuda_runtime.h>
#include <stdint.h>

// Problem shapes (fixed by the dataset)
#define B 32
#define T 8192
#define D 128
#define P 1024

// Scratch: exclusive prefix (start frame) of each phoneme, per batch.
__device__ int g_starts[B * P];

// ---------------------------------------------------------------------------
// Kernel 1: per-batch exclusive scan of durations (int32 values in [0,9)).
// One block per batch, 1024 threads, Hillis-Steele inclusive scan in smem,
// then convert to exclusive.
// ---------------------------------------------------------------------------
__global__ void scan_kernel(const int* __restrict__ dur) {
    __shared__ int s[P];
    const int b = blockIdx.x;
    const int p = threadIdx.x;

    int v = dur[b * P + p];
    s[p] = v;
    __syncthreads();

    // Hillis-Steele inclusive scan (read-all / barrier / write-all / barrier)
    #pragma unroll
    for (int off = 1; off < P; off <<= 1) {
        int add = (p >= off) ? s[p - off] : 0;
        __syncthreads();
        s[p] += add;
        __syncthreads();
    }

    // exclusive = inclusive - own value
    g_starts[b * P + p] = s[p] - v;
}

// ---------------------------------------------------------------------------
// Kernel 2: one warp per phoneme. Lane l owns channels [4l, 4l+4) via float4.
// Sum frames [start, start+d), scale by 1/d (0 if d==0), write coalesced.
// ---------------------------------------------------------------------------
__global__ void __launch_bounds__(128) avg_kernel(
    const float* __restrict__ mel,
    const int* __restrict__ dur,
    float* __restrict__ out)
{
    const int warp_in_blk = threadIdx.x >> 5;
    const int lane        = threadIdx.x & 31;
    const int gwarp       = blockIdx.x * 4 + warp_in_blk;  // global phoneme idx
    const int b           = gwarp >> 10;                   // / P
    const int p           = gwarp & (P - 1);               // % P

    const int d = dur[b * P + p];
    const int s = g_starts[b * P + p];

    // Base pointer to frame `s` of batch b, this lane's float4 within the frame.
    const float4* __restrict__ base =
        reinterpret_cast<const float4*>(mel + ((size_t)b * T + s) * D) + lane;

    float4 acc = make_float4(0.f, 0.f, 0.f, 0.f);
    #pragma unroll 8
    for (int f = 0; f < d; ++f) {
        float4 v = base[(size_t)f * (D / 4)];
        acc.x += v.x; acc.y += v.y; acc.z += v.z; acc.w += v.w;
    }

    const float inv = (d > 0) ? (1.0f / (float)d) : 0.0f;
    acc.x *= inv; acc.y *= inv; acc.z *= inv; acc.w *= inv;

    float4* __restrict__ o =
        reinterpret_cast<float4*>(out + ((size_t)b * P + p) * D) + lane;
    *o = acc;
}

extern "C" void kernel_launch(void* const* d_in, const int* in_sizes, int n_in,
                              void* d_out, int out_size) {
    const float* mel = (const float*)d_in[0];
    const int*   dur = (const int*)d_in[1];
    float*       out = (float*)d_out;

    scan_kernel<<<B, P>>>(dur);
    avg_kernel<<<(B * P) / 4, 128>>>(mel, dur, out);
}

// round 3
// speedup vs baseline: 1.1737x; 1.1737x over previous
#include <cuda_runtime.h>
#include <stdint.h>

// Problem shapes (fixed by the dataset)
#define B 32
#define T 8192
#define D 128
#define P 1024

// Scratch: exclusive prefix (start frame) of each phoneme, per batch.
__device__ int g_starts[B * P];

// ---------------------------------------------------------------------------
// Kernel 1: per-batch exclusive scan of durations (int32 values in [0,9)).
// One block per batch, 1024 threads. Warp shfl scan + single cross-warp pass.
// ---------------------------------------------------------------------------
__global__ void __launch_bounds__(1024) scan_kernel(const int* __restrict__ dur) {
    __shared__ int warp_sums[32];
    const int b    = blockIdx.x;
    const int p    = threadIdx.x;
    const int lane = p & 31;
    const int wid  = p >> 5;

    int v = dur[b * P + p];

    // inclusive scan within warp
    int x = v;
    #pragma unroll
    for (int off = 1; off < 32; off <<= 1) {
        int y = __shfl_up_sync(0xFFFFFFFFu, x, off);
        if (lane >= off) x += y;
    }
    if (lane == 31) warp_sums[wid] = x;
    __syncthreads();

    // warp 0 scans the 32 warp totals (exclusive)
    if (wid == 0) {
        int s = warp_sums[lane];
        int t = s;
        #pragma unroll
        for (int off = 1; off < 32; off <<= 1) {
            int y = __shfl_up_sync(0xFFFFFFFFu, t, off);
            if (lane >= off) t += y;
        }
        warp_sums[lane] = t - s;  // exclusive prefix of warp totals
    }
    __syncthreads();

    // exclusive result = warp base + (inclusive-in-warp - own)
    g_starts[b * P + p] = warp_sums[wid] + x - v;
}

// ---------------------------------------------------------------------------
// Kernel 2: one warp per phoneme. Lane l owns channels [4l, 4l+4) via float4.
// d <= 8 always, so fully unroll with predication: 8 front-batched LDG.128
// per lane -> MLP ~8, maximal latency hiding.
// ---------------------------------------------------------------------------
__global__ void __launch_bounds__(256) avg_kernel(
    const float* __restrict__ mel,
    const int* __restrict__ dur,
    float* __restrict__ out)
{
    const int warp_in_blk = threadIdx.x >> 5;
    const int lane        = threadIdx.x & 31;
    const int gwarp       = blockIdx.x * 8 + warp_in_blk;  // global phoneme idx
    const int b           = gwarp >> 10;                   // / P
    const int p           = gwarp & (P - 1);               // % P

    const int d = dur[b * P + p];
    const int s = g_starts[b * P + p];

    const float4* __restrict__ base =
        reinterpret_cast<const float4*>(mel + ((size_t)b * T + s) * D) + lane;

    float4 acc = make_float4(0.f, 0.f, 0.f, 0.f);
    #pragma unroll
    for (int f = 0; f < 8; ++f) {
        if (f < d) {
            float4 v = base[f * (D / 4)];
            acc.x += v.x; acc.y += v.y; acc.z += v.z; acc.w += v.w;
        }
    }

    const float inv = (d > 0) ? (1.0f / (float)d) : 0.0f;
    acc.x *= inv; acc.y *= inv; acc.z *= inv; acc.w *= inv;

    float4* __restrict__ o =
        reinterpret_cast<float4*>(out + ((size_t)b * P + p) * D) + lane;
    *o = acc;
}

extern "C" void kernel_launch(void* const* d_in, const int* in_sizes, int n_in,
                              void* d_out, int out_size) {
    const float* mel = (const float*)d_in[0];
    const int*   dur = (const int*)d_in[1];
    float*       out = (float*)d_out;

    scan_kernel<<<B, P>>>(dur);
    avg_kernel<<<(B * P) / 8, 256>>>(mel, dur, out);
}

// round 4
// speedup vs baseline: 1.3175x; 1.1225x over previous
#include <cuda_runtime.h>
#include <stdint.h>

// Problem shapes (fixed by the dataset)
#define B 32
#define T 8192
#define D 128
#define P 1024
#define WIN 8        // phonemes per block (one per warp)
#define THREADS 256

// ---------------------------------------------------------------------------
// Fused kernel: each block
//   1) cooperatively loads its batch's 1024 durations (int4 per thread),
//   2) block-exclusive-scans them (shfl warp scan + cross-warp pass),
//   3) each warp gathers/averages one phoneme's frames (d <= 8, fully
//      unrolled predicated LDG.128 batch -> MLP ~8 per warp).
// ---------------------------------------------------------------------------
__global__ void __launch_bounds__(THREADS) fused_kernel(
    const float* __restrict__ mel,
    const int*   __restrict__ dur,
    float*       __restrict__ out)
{
    __shared__ int s_dur[P];          // this batch's durations
    __shared__ int s_pref[THREADS];   // exclusive prefix at 4-element groups
    __shared__ int s_wsum[THREADS / 32];

    const int b    = blockIdx.x >> 7;     // P/WIN = 128 windows per batch
    const int win  = blockIdx.x & 127;
    const int t    = threadIdx.x;
    const int lane = t & 31;
    const int wid  = t >> 5;

    // --- cooperative duration load: thread t owns elements [4t, 4t+4) ---
    int4 dv = reinterpret_cast<const int4*>(dur + b * P)[t];
    reinterpret_cast<int4*>(s_dur)[t] = dv;
    const int tsum = dv.x + dv.y + dv.z + dv.w;

    // --- warp inclusive scan of per-thread group sums ---
    int x = tsum;
    #pragma unroll
    for (int off = 1; off < 32; off <<= 1) {
        int y = __shfl_up_sync(0xFFFFFFFFu, x, off);
        if (lane >= off) x += y;
    }
    if (lane == 31) s_wsum[wid] = x;
    __syncthreads();

    // --- warp 0 exclusive-scans the 8 warp totals ---
    if (wid == 0) {
        int s  = (lane < THREADS / 32) ? s_wsum[lane] : 0;
        int tt = s;
        #pragma unroll
        for (int off = 1; off < THREADS / 32; off <<= 1) {
            int y = __shfl_up_sync(0xFFFFFFFFu, tt, off);
            if (lane >= off) tt += y;
        }
        if (lane < THREADS / 32) s_wsum[lane] = tt - s;
    }
    __syncthreads();

    // exclusive prefix before thread t's 4-element group
    s_pref[t] = s_wsum[wid] + x - tsum;
    __syncthreads();

    // --- each warp resolves (start, d) for its phoneme ---
    const int p = win * WIN + wid;
    const int g = p >> 2;
    const int r = p & 3;
    int st = s_pref[g];
    #pragma unroll
    for (int k = 0; k < 3; ++k)
        if (k < r) st += s_dur[g * 4 + k];
    const int d = s_dur[p];

    // --- gather: lane l owns channels [4l, 4l+4) via float4 ---
    const float4* __restrict__ base =
        reinterpret_cast<const float4*>(mel + ((size_t)b * T + st) * D) + lane;

    float4 acc = make_float4(0.f, 0.f, 0.f, 0.f);
    #pragma unroll
    for (int f = 0; f < 8; ++f) {
        if (f < d) {
            float4 v = base[f * (D / 4)];
            acc.x += v.x; acc.y += v.y; acc.z += v.z; acc.w += v.w;
        }
    }

    const float inv = (d > 0) ? (1.0f / (float)d) : 0.0f;
    acc.x *= inv; acc.y *= inv; acc.z *= inv; acc.w *= inv;

    __stcs(reinterpret_cast<float4*>(out + ((size_t)b * P + p) * D) + lane, acc);
}

extern "C" void kernel_launch(void* const* d_in, const int* in_sizes, int n_in,
                              void* d_out, int out_size) {
    const float* mel = (const float*)d_in[0];
    const int*   dur = (const int*)d_in[1];
    float*       out = (float*)d_out;

    fused_kernel<<<(B * P) / WIN, THREADS>>>(mel, dur, out);
}

// round 5
// speedup vs baseline: 1.3208x; 1.0025x over previous
#include <cuda_runtime.h>
#include <stdint.h>

// Problem shapes (fixed by the dataset)
#define B 32
#define T 8192
#define D 128
#define P 1024
#define WIN 16       // phonemes per block (two per warp)
#define THREADS 256

// ---------------------------------------------------------------------------
// Fused kernel: each block
//   1) cooperatively loads its batch's 1024 durations (int4 per thread),
//   2) block-exclusive-scans them (shfl warp scan + cross-warp pass),
//   3) each warp gathers/averages TWO consecutive phonemes (d <= 8 each,
//      fully unrolled predicated LDG.128 -> up to 16 loads in flight/warp).
// ---------------------------------------------------------------------------
__global__ void __launch_bounds__(THREADS) fused_kernel(
    const float* __restrict__ mel,
    const int*   __restrict__ dur,
    float*       __restrict__ out)
{
    __shared__ int s_dur[P];          // this batch's durations
    __shared__ int s_pref[THREADS];   // exclusive prefix at 4-element groups
    __shared__ int s_wsum[THREADS / 32];

    const int b    = blockIdx.x >> 6;     // P/WIN = 64 windows per batch
    const int win  = blockIdx.x & 63;
    const int t    = threadIdx.x;
    const int lane = t & 31;
    const int wid  = t >> 5;

    // --- cooperative duration load: thread t owns elements [4t, 4t+4) ---
    int4 dv = reinterpret_cast<const int4*>(dur + b * P)[t];
    reinterpret_cast<int4*>(s_dur)[t] = dv;
    const int tsum = dv.x + dv.y + dv.z + dv.w;

    // --- warp inclusive scan of per-thread group sums ---
    int x = tsum;
    #pragma unroll
    for (int off = 1; off < 32; off <<= 1) {
        int y = __shfl_up_sync(0xFFFFFFFFu, x, off);
        if (lane >= off) x += y;
    }
    if (lane == 31) s_wsum[wid] = x;
    __syncthreads();

    // --- warp 0 exclusive-scans the 8 warp totals ---
    if (wid == 0) {
        int s  = (lane < THREADS / 32) ? s_wsum[lane] : 0;
        int tt = s;
        #pragma unroll
        for (int off = 1; off < THREADS / 32; off <<= 1) {
            int y = __shfl_up_sync(0xFFFFFFFFu, tt, off);
            if (lane >= off) tt += y;
        }
        if (lane < THREADS / 32) s_wsum[lane] = tt - s;
    }
    __syncthreads();

    // exclusive prefix before thread t's 4-element group
    s_pref[t] = s_wsum[wid] + x - tsum;
    __syncthreads();

    // --- each warp resolves (start, d) for its two consecutive phonemes ---
    const int p0 = win * WIN + wid * 2;       // and p0 + 1
    const int g  = p0 >> 2;
    const int r  = p0 & 3;
    int st0 = s_pref[g];
    #pragma unroll
    for (int k = 0; k < 3; ++k)
        if (k < r) st0 += s_dur[g * 4 + k];
    const int d0  = s_dur[p0];
    const int d1  = s_dur[p0 + 1];
    const int st1 = st0 + d0;

    // --- gather: lane l owns channels [4l, 4l+4) via float4 ---
    const float4* __restrict__ base0 =
        reinterpret_cast<const float4*>(mel + ((size_t)b * T + st0) * D) + lane;
    const float4* __restrict__ base1 =
        reinterpret_cast<const float4*>(mel + ((size_t)b * T + st1) * D) + lane;

    float4 a0 = make_float4(0.f, 0.f, 0.f, 0.f);
    float4 a1 = make_float4(0.f, 0.f, 0.f, 0.f);
    #pragma unroll
    for (int f = 0; f < 8; ++f) {
        if (f < d0) {
            float4 v = __ldcs(base0 + f * (D / 4));
            a0.x += v.x; a0.y += v.y; a0.z += v.z; a0.w += v.w;
        }
        if (f < d1) {
            float4 v = __ldcs(base1 + f * (D / 4));
            a1.x += v.x; a1.y += v.y; a1.z += v.z; a1.w += v.w;
        }
    }

    const float i0 = (d0 > 0) ? (1.0f / (float)d0) : 0.0f;
    const float i1 = (d1 > 0) ? (1.0f / (float)d1) : 0.0f;
    a0.x *= i0; a0.y *= i0; a0.z *= i0; a0.w *= i0;
    a1.x *= i1; a1.y *= i1; a1.z *= i1; a1.w *= i1;

    float4* __restrict__ o =
        reinterpret_cast<float4*>(out + ((size_t)b * P + p0) * D) + lane;
    __stcs(o, a0);
    __stcs(o + (D / 4), a1);
}

extern "C" void kernel_launch(void* const* d_in, const int* in_sizes, int n_in,
                              void* d_out, int out_size) {
    const float* mel = (const float*)d_in[0];
    const int*   dur = (const int*)d_in[1];
    float*       out = (float*)d_out;

    fused_kernel<<<(B * P) / WIN, THREADS>>>(mel, dur, out);
}